// round 14
// baseline (speedup 1.0000x reference)
#include <cuda_runtime.h>
#include <cuda_fp16.h>
#include <math.h>

#define NN   100000
#define EMAX 3200000
#define FIN  256
#define CH   16
#define NL   7
#define PAD  96          // bucket capacity; P(any deg>96) ~ 1e-13 for Poisson(32)
#define NSM  148

#define RPB  512         // gemm1 rows per block
#define CCH  16          // gemm1 columns per smem chunk
#define XS_STRIDE 513    // 513 % 32 == 1 -> conflict-free lane-contiguous reads
#define GEMM_SMEM ((FIN * CH + CCH * XS_STRIDE) * sizeof(float))   // 49216 B

// ---------------- scratch (static __device__, no cudaMalloc) ----------------
// Invariant: g_deg all-zero at entry of every launch (static init covers call 1;
// k_conv2 resets it at the end of each launch).
__device__ int g_deg[NN];
__device__ __align__(128) int    g_buf[NN * PAD + 16];  // +16 pad for coop tail reads
__device__ __align__(16)  __half g_h[NN * CH];      // x@W0 fp16 (unscaled, then scaled in place)
__device__ __align__(16)  __half g_h2[NN * 8];      // dinv-scaled layer-2 input, fp16 [N,8]

// ---------------- packed f32x2 helpers --------------------------------------
__device__ __forceinline__ void ffma2(unsigned long long& d,
                                      unsigned long long a, unsigned long long b) {
    asm("fma.rn.f32x2 %0, %1, %2, %0;" : "+l"(d) : "l"(a), "l"(b));
}
__device__ __forceinline__ unsigned long long pack2(float v) {
    unsigned long long r;
    asm("mov.b64 %0, {%1, %1};" : "=l"(r) : "f"(v));
    return r;
}
__device__ __forceinline__ float2 unpack2(unsigned long long v) {
    float2 r;
    asm("mov.b64 {%0, %1}, %2;" : "=f"(r.x), "=f"(r.y) : "l"(v));
    return r;
}

// ---------------- 1. scatter edges into padded buckets (int4, 4 edges/thr) --
__global__ void k_fill(const int* __restrict__ src, const int* __restrict__ dst,
                       int E, int Q) {
    int i = blockIdx.x * blockDim.x + threadIdx.x;
    if (i >= Q) return;
    int b = i * 4;
    if (b + 3 < E) {
        int4 s4 = __ldg((const int4*)src + i);
        int4 d4 = __ldg((const int4*)dst + i);
        int p0 = atomicAdd(&g_deg[d4.x], 1);
        if (p0 < PAD) g_buf[d4.x * PAD + p0] = s4.x;
        int p1 = atomicAdd(&g_deg[d4.y], 1);
        if (p1 < PAD) g_buf[d4.y * PAD + p1] = s4.y;
        int p2 = atomicAdd(&g_deg[d4.z], 1);
        if (p2 < PAD) g_buf[d4.z * PAD + p2] = s4.z;
        int p3 = atomicAdd(&g_deg[d4.w], 1);
        if (p3 < PAD) g_buf[d4.w * PAD + p3] = s4.w;
    } else {
        for (int j = b; j < E; j++) {
            int s = src[j], d = dst[j];
            int pos = atomicAdd(&g_deg[d], 1);
            if (pos < PAD) g_buf[d * PAD + pos] = s;
        }
    }
}

// ---------------- 2. h = x @ W0 (UNSCALED), fp16 out, smem-tiled ------------
// Block handles 512 rows (2 per thread). x staged per 16-col chunk through a
// TRANSPOSED smem tile xs[c][513] so gmem loads are 64B-contiguous per warp
// and compute reads are lane-contiguous (conflict-free). W0 broadcast from smem.
// Runs concurrently with k_fill (does not touch g_deg).
__global__ void __launch_bounds__(256) k_gemm1(const float* __restrict__ x,
                                               const float* __restrict__ W0) {
    extern __shared__ float dyn[];
    float* W0s = dyn;                      // [FIN*CH] = 16KB
    float* xs  = dyn + FIN * CH;           // [CCH * XS_STRIDE]

    int t = threadIdx.x;
    for (int i = t; i < FIN * CH; i += 256) W0s[i] = W0[i];

    int row0 = blockIdx.x * RPB;
    int rA = row0 + t;                     // this thread's two rows
    int rB = row0 + 256 + t;

    unsigned long long accA[8], accB[8];
    #pragma unroll
    for (int j = 0; j < 8; j++) { accA[j] = 0ull; accB[j] = 0ull; }

    for (int ch = 0; ch < FIN / CCH; ch++) {
        __syncthreads();                   // xs reuse: previous compute done
        // cooperative load: 512 rows x 16 cols, transposed into xs
        for (int i = t; i < RPB * CCH; i += 256) {
            int r = i >> 4, c = i & 15;    // warp = 2 rows x 16 cols: 64B segs
            int gr = row0 + r;
            float v = (gr < NN) ? __ldg(&x[(size_t)gr * FIN + ch * CCH + c]) : 0.f;
            xs[c * XS_STRIDE + r] = v;
        }
        __syncthreads();
        #pragma unroll 4
        for (int c = 0; c < CCH; c++) {
            unsigned long long xpA = pack2(xs[c * XS_STRIDE + t]);
            unsigned long long xpB = pack2(xs[c * XS_STRIDE + 256 + t]);
            const unsigned long long* wr =
                (const unsigned long long*)(W0s + (size_t)(ch * CCH + c) * CH);
            #pragma unroll
            for (int jj = 0; jj < 8; jj++) {
                ffma2(accA[jj], xpA, wr[jj]);
                ffma2(accB[jj], xpB, wr[jj]);
            }
        }
    }

    __half2 hv[8];
    if (rA < NN) {
        #pragma unroll
        for (int j = 0; j < 8; j++) {
            float2 p = unpack2(accA[j]);
            hv[j] = __floats2half2_rn(p.x, p.y);
        }
        uint4* hr = (uint4*)(g_h + (size_t)rA * CH);
        hr[0] = *(uint4*)&hv[0];
        hr[1] = *(uint4*)&hv[4];
    }
    if (rB < NN) {
        #pragma unroll
        for (int j = 0; j < 8; j++) {
            float2 p = unpack2(accB[j]);
            hv[j] = __floats2half2_rn(p.x, p.y);
        }
        uint4* hr = (uint4*)(g_h + (size_t)rB * CH);
        hr[0] = *(uint4*)&hv[0];
        hr[1] = *(uint4*)&hv[4];
    }
}

// ---------------- 3. scale h rows in place by dinv[row] ---------------------
__global__ void k_scale() {
    int i = blockIdx.x * 256 + threadIdx.x;      // NN*8 half2 words
    if (i >= NN * 8) return;
    int r = i >> 3;
    float s = rsqrtf((float)(g_deg[r] + 1));     // +1 = self loop
    __half2* H = (__half2*)g_h;
    float2 v = __half22float2(H[i]);
    H[i] = __floats2half2_rn(v.x * s, v.y * s);
}

// ---------------- 4. conv1 + relu + 16->7 dense, fused (persistent) ---------
// 4 lanes per node (8 nodes/warp), grid-stride over nodes. Lane q holds
// features 4q..4q+3 via one 8-byte gather.
__global__ void __launch_bounds__(256, 6) k_conv1(const float* __restrict__ W1) {
    __shared__ float W1s[CH * NL];
    int t = threadIdx.x;
    if (t < CH * NL) W1s[t] = W1[t];
    __syncthreads();

    int lane = t & 31;
    int q    = lane & 3;                              // feature-quad index
    int base = lane & 28;                             // group base within warp
    unsigned gmask = 0xFu << base;                    // 4-lane group mask
    int node0  = (blockIdx.x * blockDim.x + t) >> 2;
    int stride = (gridDim.x * blockDim.x) >> 2;

    const unsigned long long* H64 = (const unsigned long long*)g_h;  // row = 4 ull
    __half2* H2o = (__half2*)g_h2;

    for (int node = node0; node < NN; node += stride) {
        int cnt = g_deg[node];
        float dinv_d = rsqrtf((float)(cnt + 1));
        const int* adj = g_buf + (size_t)node * PAD;

        // self-loop term (row pre-scaled by dinv[src])
        unsigned long long sw = __ldg(&H64[(size_t)node * 4 + q]);
        float2 slo = __half22float2(*(__half2*)&sw);
        float2 shi = __half22float2(*((__half2*)&sw + 1));
        float a0 = slo.x, a1 = slo.y, a2 = shi.x, a3 = shi.y;
        float b0 = 0.f, b1 = 0.f, b2 = 0.f, b3 = 0.f;

        int n4 = cnt & ~3;
        int e = 0;
        for (; e < n4; e += 4) {
            int my = __ldg(&adj[e + q]);              // 16B per group
            int s0 = __shfl_sync(gmask, my, base + 0);
            int s1 = __shfl_sync(gmask, my, base + 1);
            int s2 = __shfl_sync(gmask, my, base + 2);
            int s3 = __shfl_sync(gmask, my, base + 3);
            unsigned long long w0 = __ldg(&H64[(size_t)s0 * 4 + q]);
            unsigned long long w1 = __ldg(&H64[(size_t)s1 * 4 + q]);
            unsigned long long w2 = __ldg(&H64[(size_t)s2 * 4 + q]);
            unsigned long long w3 = __ldg(&H64[(size_t)s3 * 4 + q]);
            float2 l0 = __half22float2(*(__half2*)&w0), h0 = __half22float2(*((__half2*)&w0 + 1));
            float2 l1 = __half22float2(*(__half2*)&w1), h1 = __half22float2(*((__half2*)&w1 + 1));
            float2 l2 = __half22float2(*(__half2*)&w2), h2 = __half22float2(*((__half2*)&w2 + 1));
            float2 l3 = __half22float2(*(__half2*)&w3), h3 = __half22float2(*((__half2*)&w3 + 1));
            a0 += l0.x; a1 += l0.y; a2 += h0.x; a3 += h0.y;
            b0 += l1.x; b1 += l1.y; b2 += h1.x; b3 += h1.y;
            a0 += l2.x; a1 += l2.y; a2 += h2.x; a3 += h2.y;
            b0 += l3.x; b1 += l3.y; b2 += h3.x; b3 += h3.y;
        }
        if (e < cnt) {                                // tail: 1..3 edges
            int rem = cnt - e;
            int my = __ldg(&adj[e + q]);              // in-bounds (padded buffer)
            #pragma unroll
            for (int j = 0; j < 3; j++) {
                int sj = __shfl_sync(gmask, my, base + j);
                if (j < rem) {
                    unsigned long long w = __ldg(&H64[(size_t)sj * 4 + q]);
                    float2 l = __half22float2(*(__half2*)&w);
                    float2 h = __half22float2(*((__half2*)&w + 1));
                    a0 += l.x; a1 += l.y; a2 += h.x; a3 += h.y;
                }
            }
        }
        float rv[4];
        rv[0] = fmaxf(dinv_d * (a0 + b0), 0.f);
        rv[1] = fmaxf(dinv_d * (a1 + b1), 0.f);
        rv[2] = fmaxf(dinv_d * (a2 + b2), 0.f);
        rv[3] = fmaxf(dinv_d * (a3 + b3), 0.f);

        // 16->7 dense: lane q produces outputs 2q, 2q+1 (out 7 -> 0)
        int j0 = 2 * q;
        int j1 = (2 * q + 1 < NL) ? 2 * q + 1 : 0;
        float o0 = 0.f, o1 = 0.f;
        #pragma unroll
        for (int m = 0; m < 4; m++) {
            float r0 = __shfl_sync(gmask, rv[0], base + m);
            float r1 = __shfl_sync(gmask, rv[1], base + m);
            float r2 = __shfl_sync(gmask, rv[2], base + m);
            float r3 = __shfl_sync(gmask, rv[3], base + m);
            o0 = fmaf(r0, W1s[(4 * m + 0) * NL + j0], o0);
            o0 = fmaf(r1, W1s[(4 * m + 1) * NL + j0], o0);
            o0 = fmaf(r2, W1s[(4 * m + 2) * NL + j0], o0);
            o0 = fmaf(r3, W1s[(4 * m + 3) * NL + j0], o0);
            o1 = fmaf(r0, W1s[(4 * m + 0) * NL + j1], o1);
            o1 = fmaf(r1, W1s[(4 * m + 1) * NL + j1], o1);
            o1 = fmaf(r2, W1s[(4 * m + 2) * NL + j1], o1);
            o1 = fmaf(r3, W1s[(4 * m + 3) * NL + j1], o1);
        }
        float hi = (2 * q + 1 < NL) ? dinv_d * o1 : 0.f;
        H2o[(size_t)node * 4 + q] = __floats2half2_rn(dinv_d * o0, hi);
    }
}

// ---------------- 5. conv2 + exp + 1; resets g_deg --------------------------
// 4 lanes per node (8 nodes/warp), half2 gathers + HADD2, direct indexing.
__global__ void k_conv2(float* __restrict__ out) {
    int t    = blockIdx.x * blockDim.x + threadIdx.x;
    int lane = threadIdx.x & 31;
    int f2   = lane & 3;
    int base = lane & 28;
    unsigned gmask = 0xFu << base;
    int node = t >> 2;
    if (node >= NN) return;

    int cnt = g_deg[node];
    const int* adj = g_buf + (size_t)node * PAD;
    const __half2* H2 = (const __half2*)g_h2;

    __half2 z2 = __floats2half2_rn(0.f, 0.f);
    __half2 c0 = H2[node * 4 + f2];                   // self-loop term
    __half2 c1 = z2, c2 = z2, c3 = z2;

    int n4 = cnt & ~3;
    int e = 0;
    for (; e < n4; e += 4) {
        int my = __ldg(&adj[e + f2]);                 // 16B per group
        int s0 = __shfl_sync(gmask, my, base + 0);
        int s1 = __shfl_sync(gmask, my, base + 1);
        int s2 = __shfl_sync(gmask, my, base + 2);
        int s3 = __shfl_sync(gmask, my, base + 3);
        c0 = __hadd2(c0, H2[s0 * 4 + f2]);
        c1 = __hadd2(c1, H2[s1 * 4 + f2]);
        c2 = __hadd2(c2, H2[s2 * 4 + f2]);
        c3 = __hadd2(c3, H2[s3 * 4 + f2]);
    }
    if (e < cnt) {
        int rem = cnt - e;                            // 1..3
        int my = __ldg(&adj[e + f2]);                 // in-bounds (padded buffer)
        #pragma unroll
        for (int j = 0; j < 3; j++) {
            int sj = __shfl_sync(gmask, my, base + j);
            if (j < rem) c0 = __hadd2(c0, H2[sj * 4 + f2]);
        }
    }
    __half2 tot = __hadd2(__hadd2(c0, c1), __hadd2(c2, c3));
    float2 sv = __half22float2(tot);

    float dinv_d = rsqrtf((float)(cnt + 1));
    out[node * NL + 2 * f2] = expf(dinv_d * sv.x) + 1.0f;
    if (f2 < 3)
        out[node * NL + 2 * f2 + 1] = expf(dinv_d * sv.y) + 1.0f;
    if (f2 == 3) g_deg[node] = 0;                     // self-clean for next launch
}

// ---------------- launcher ---------------------------------------------------
extern "C" void kernel_launch(void* const* d_in, const int* in_sizes, int n_in,
                              void* d_out, int out_size) {
    const float* x  = (const float*)d_in[0];   // [N,256]
    const float* W0 = (const float*)d_in[1];   // [256,16]
    const float* W1 = (const float*)d_in[2];   // [16,7]
    const int*   ei = (const int*)d_in[3];     // [2,E]
    int E = in_sizes[3] / 2;
    const int* src = ei;
    const int* dst = ei + E;
    float* out = (float*)d_out;

    // Lazily created side stream + events for a fork-join inside graph capture.
    // One-time cudaFuncSetAttribute for gemm1's 49KB dynamic smem (host-side only).
    static cudaStream_t s2 = nullptr;
    static cudaEvent_t evFork = nullptr, evJoin = nullptr;
    if (s2 == nullptr) {
        cudaStreamCreateWithFlags(&s2, cudaStreamNonBlocking);
        cudaEventCreateWithFlags(&evFork, cudaEventDisableTiming);
        cudaEventCreateWithFlags(&evJoin, cudaEventDisableTiming);
        cudaFuncSetAttribute(k_gemm1, cudaFuncAttributeMaxDynamicSharedMemorySize,
                             (int)GEMM_SMEM);
    }

    int Q = (E + 3) / 4;
    int gemmBlocks = (NN + RPB - 1) / RPB;           // 196

    // fork: gemm1 (unscaled, independent of g_deg) runs concurrently with fill
    cudaEventRecord(evFork, 0);
    cudaStreamWaitEvent(s2, evFork, 0);
    k_gemm1 <<<gemmBlocks, 256, GEMM_SMEM, s2>>>(x, W0);
    k_fill  <<<(Q + 255) / 256, 256>>>(src, dst, E, Q);
    cudaEventRecord(evJoin, s2);
    cudaStreamWaitEvent(0, evJoin, 0);
    // join: everything below depends on both branches
    k_scale <<<(NN * 8 + 255) / 256, 256>>>();
    k_conv1 <<<NSM * 6, 256>>>(W1);                  // persistent: exactly 1 wave
    k_conv2 <<<(NN * 4 + 255) / 256, 256>>>(out);
}

// round 15
// speedup vs baseline: 1.0439x; 1.0439x over previous
#include <cuda_runtime.h>
#include <cuda_fp16.h>
#include <math.h>

#define NN   100000
#define EMAX 3200000
#define FIN  256
#define CH   16
#define NL   7
#define PAD  96          // bucket capacity; P(any deg>96) ~ 1e-13 for Poisson(32)
#define NSM  148

// ---------------- scratch (static __device__, no cudaMalloc) ----------------
// Invariant: g_deg all-zero at entry of every launch (static init covers call 1;
// k_conv2 resets it at the end of each launch).
__device__ int g_deg[NN];
__device__ __align__(128) int    g_buf[NN * PAD + 16];  // +16 pad for coop tail reads
__device__ __align__(16)  __half g_h[NN * CH];      // x@W0 fp16 (unscaled, then scaled in place)
__device__ __align__(16)  __half g_h2[NN * 8];      // dinv-scaled layer-2 input, fp16 [N,8]

// ---------------- packed f32x2 helpers --------------------------------------
__device__ __forceinline__ void ffma2(unsigned long long& d,
                                      unsigned long long a, unsigned long long b) {
    asm("fma.rn.f32x2 %0, %1, %2, %0;" : "+l"(d) : "l"(a), "l"(b));
}
__device__ __forceinline__ unsigned long long pack2(float v) {
    unsigned long long r;
    asm("mov.b64 %0, {%1, %1};" : "=l"(r) : "f"(v));
    return r;
}
__device__ __forceinline__ float2 unpack2(unsigned long long v) {
    float2 r;
    asm("mov.b64 {%0, %1}, %2;" : "=f"(r.x), "=f"(r.y) : "l"(v));
    return r;
}

// ---------------- 1. scatter edges into padded buckets (int4, 4 edges/thr) --
__global__ void k_fill(const int* __restrict__ src, const int* __restrict__ dst,
                       int E, int Q) {
    int i = blockIdx.x * blockDim.x + threadIdx.x;
    if (i >= Q) return;
    int b = i * 4;
    if (b + 3 < E) {
        int4 s4 = __ldg((const int4*)src + i);
        int4 d4 = __ldg((const int4*)dst + i);
        int p0 = atomicAdd(&g_deg[d4.x], 1);
        if (p0 < PAD) g_buf[d4.x * PAD + p0] = s4.x;
        int p1 = atomicAdd(&g_deg[d4.y], 1);
        if (p1 < PAD) g_buf[d4.y * PAD + p1] = s4.y;
        int p2 = atomicAdd(&g_deg[d4.z], 1);
        if (p2 < PAD) g_buf[d4.z * PAD + p2] = s4.z;
        int p3 = atomicAdd(&g_deg[d4.w], 1);
        if (p3 < PAD) g_buf[d4.w * PAD + p3] = s4.w;
    } else {
        for (int j = b; j < E; j++) {
            int s = src[j], d = dst[j];
            int pos = atomicAdd(&g_deg[d], 1);
            if (pos < PAD) g_buf[d * PAD + pos] = s;
        }
    }
}

// ---------------- 2. h = x @ W0 (UNSCALED), fp16 out, f32x2 FMA (R12) -------
// Runs concurrently with k_fill (does not touch g_deg).
__global__ void k_gemm1(const float* __restrict__ x, const float* __restrict__ W0) {
    __shared__ __align__(16) float W0s[FIN * CH];
    int t = threadIdx.x;
    for (int i = t; i < FIN * CH; i += 256) W0s[i] = W0[i];
    __syncthreads();
    int r = blockIdx.x * 256 + t;
    if (r >= NN) return;

    const float4* xr = (const float4*)(x + (size_t)r * FIN);
    const unsigned long long* W8 = (const unsigned long long*)W0s;

    unsigned long long acc2[8];
    #pragma unroll
    for (int j = 0; j < 8; j++) acc2[j] = 0ull;

    #pragma unroll 4
    for (int i4 = 0; i4 < FIN / 4; i4++) {
        float4 v = xr[i4];
        #pragma unroll
        for (int k = 0; k < 4; k++) {
            float xv = (k == 0) ? v.x : (k == 1) ? v.y : (k == 2) ? v.z : v.w;
            unsigned long long xp = pack2(xv);
            const unsigned long long* wr = W8 + (size_t)(i4 * 4 + k) * 8;
            #pragma unroll
            for (int j = 0; j < 8; j++) ffma2(acc2[j], xp, wr[j]);
        }
    }
    __half2 hv[8];
    #pragma unroll
    for (int j = 0; j < 8; j++) {
        float2 p = unpack2(acc2[j]);
        hv[j] = __floats2half2_rn(p.x, p.y);
    }
    uint4* hr = (uint4*)(g_h + (size_t)r * CH);
    hr[0] = *(uint4*)&hv[0];
    hr[1] = *(uint4*)&hv[4];
}

// ---------------- 3. scale h rows in place by dinv[row], uint4 --------------
__global__ void k_scale() {
    int i = blockIdx.x * 256 + threadIdx.x;      // NN*2 uint4 words (8 halfs each)
    if (i >= NN * 2) return;
    int r = i >> 1;
    float s = rsqrtf((float)(g_deg[r] + 1));     // +1 = self loop
    uint4 v = ((const uint4*)g_h)[i];
    __half2* hp = (__half2*)&v;
    #pragma unroll
    for (int j = 0; j < 4; j++) {
        float2 p = __half22float2(hp[j]);
        hp[j] = __floats2half2_rn(p.x * s, p.y * s);
    }
    ((uint4*)g_h)[i] = v;
}

// ---------------- 4. conv1 + relu + 16->7 dense, fused (persistent) ---------
// 4 lanes per node (8 nodes/warp), grid-stride over nodes. Lane q holds
// features 4q..4q+3 via one 8-byte gather.
__global__ void __launch_bounds__(256, 6) k_conv1(const float* __restrict__ W1) {
    __shared__ float W1s[CH * NL];
    int t = threadIdx.x;
    if (t < CH * NL) W1s[t] = W1[t];
    __syncthreads();

    int lane = t & 31;
    int q    = lane & 3;                              // feature-quad index
    int base = lane & 28;                             // group base within warp
    unsigned gmask = 0xFu << base;                    // 4-lane group mask
    int node0  = (blockIdx.x * blockDim.x + t) >> 2;
    int stride = (gridDim.x * blockDim.x) >> 2;

    const unsigned long long* H64 = (const unsigned long long*)g_h;  // row = 4 ull
    __half2* H2o = (__half2*)g_h2;

    for (int node = node0; node < NN; node += stride) {
        int cnt = g_deg[node];
        float dinv_d = rsqrtf((float)(cnt + 1));
        const int* adj = g_buf + (size_t)node * PAD;

        // self-loop term (row pre-scaled by dinv[src])
        unsigned long long sw = __ldg(&H64[(size_t)node * 4 + q]);
        float2 slo = __half22float2(*(__half2*)&sw);
        float2 shi = __half22float2(*((__half2*)&sw + 1));
        float a0 = slo.x, a1 = slo.y, a2 = shi.x, a3 = shi.y;
        float b0 = 0.f, b1 = 0.f, b2 = 0.f, b3 = 0.f;

        int n4 = cnt & ~3;
        int e = 0;
        for (; e < n4; e += 4) {
            int my = __ldg(&adj[e + q]);              // 16B per group
            int s0 = __shfl_sync(gmask, my, base + 0);
            int s1 = __shfl_sync(gmask, my, base + 1);
            int s2 = __shfl_sync(gmask, my, base + 2);
            int s3 = __shfl_sync(gmask, my, base + 3);
            unsigned long long w0 = __ldg(&H64[(size_t)s0 * 4 + q]);
            unsigned long long w1 = __ldg(&H64[(size_t)s1 * 4 + q]);
            unsigned long long w2 = __ldg(&H64[(size_t)s2 * 4 + q]);
            unsigned long long w3 = __ldg(&H64[(size_t)s3 * 4 + q]);
            float2 l0 = __half22float2(*(__half2*)&w0), h0 = __half22float2(*((__half2*)&w0 + 1));
            float2 l1 = __half22float2(*(__half2*)&w1), h1 = __half22float2(*((__half2*)&w1 + 1));
            float2 l2 = __half22float2(*(__half2*)&w2), h2 = __half22float2(*((__half2*)&w2 + 1));
            float2 l3 = __half22float2(*(__half2*)&w3), h3 = __half22float2(*((__half2*)&w3 + 1));
            a0 += l0.x; a1 += l0.y; a2 += h0.x; a3 += h0.y;
            b0 += l1.x; b1 += l1.y; b2 += h1.x; b3 += h1.y;
            a0 += l2.x; a1 += l2.y; a2 += h2.x; a3 += h2.y;
            b0 += l3.x; b1 += l3.y; b2 += h3.x; b3 += h3.y;
        }
        if (e < cnt) {                                // tail: 1..3 edges
            int rem = cnt - e;
            int my = __ldg(&adj[e + q]);              // in-bounds (padded buffer)
            #pragma unroll
            for (int j = 0; j < 3; j++) {
                int sj = __shfl_sync(gmask, my, base + j);
                if (j < rem) {
                    unsigned long long w = __ldg(&H64[(size_t)sj * 4 + q]);
                    float2 l = __half22float2(*(__half2*)&w);
                    float2 h = __half22float2(*((__half2*)&w + 1));
                    a0 += l.x; a1 += l.y; a2 += h.x; a3 += h.y;
                }
            }
        }
        float rv[4];
        rv[0] = fmaxf(dinv_d * (a0 + b0), 0.f);
        rv[1] = fmaxf(dinv_d * (a1 + b1), 0.f);
        rv[2] = fmaxf(dinv_d * (a2 + b2), 0.f);
        rv[3] = fmaxf(dinv_d * (a3 + b3), 0.f);

        // 16->7 dense: lane q produces outputs 2q, 2q+1 (out 7 -> 0)
        int j0 = 2 * q;
        int j1 = (2 * q + 1 < NL) ? 2 * q + 1 : 0;
        float o0 = 0.f, o1 = 0.f;
        #pragma unroll
        for (int m = 0; m < 4; m++) {
            float r0 = __shfl_sync(gmask, rv[0], base + m);
            float r1 = __shfl_sync(gmask, rv[1], base + m);
            float r2 = __shfl_sync(gmask, rv[2], base + m);
            float r3 = __shfl_sync(gmask, rv[3], base + m);
            o0 = fmaf(r0, W1s[(4 * m + 0) * NL + j0], o0);
            o0 = fmaf(r1, W1s[(4 * m + 1) * NL + j0], o0);
            o0 = fmaf(r2, W1s[(4 * m + 2) * NL + j0], o0);
            o0 = fmaf(r3, W1s[(4 * m + 3) * NL + j0], o0);
            o1 = fmaf(r0, W1s[(4 * m + 0) * NL + j1], o1);
            o1 = fmaf(r1, W1s[(4 * m + 1) * NL + j1], o1);
            o1 = fmaf(r2, W1s[(4 * m + 2) * NL + j1], o1);
            o1 = fmaf(r3, W1s[(4 * m + 3) * NL + j1], o1);
        }
        float hi = (2 * q + 1 < NL) ? dinv_d * o1 : 0.f;
        H2o[(size_t)node * 4 + q] = __floats2half2_rn(dinv_d * o0, hi);
    }
}

// ---------------- 5. conv2 + exp + 1; resets g_deg --------------------------
// 4 lanes per node (8 nodes/warp), half2 gathers + HADD2, direct indexing.
__global__ void k_conv2(float* __restrict__ out) {
    int t    = blockIdx.x * blockDim.x + threadIdx.x;
    int lane = threadIdx.x & 31;
    int f2   = lane & 3;
    int base = lane & 28;
    unsigned gmask = 0xFu << base;
    int node = t >> 2;
    if (node >= NN) return;

    int cnt = g_deg[node];
    const int* adj = g_buf + (size_t)node * PAD;
    const __half2* H2 = (const __half2*)g_h2;

    __half2 z2 = __floats2half2_rn(0.f, 0.f);
    __half2 c0 = H2[node * 4 + f2];                   // self-loop term
    __half2 c1 = z2, c2 = z2, c3 = z2;

    int n4 = cnt & ~3;
    int e = 0;
    for (; e < n4; e += 4) {
        int my = __ldg(&adj[e + f2]);                 // 16B per group
        int s0 = __shfl_sync(gmask, my, base + 0);
        int s1 = __shfl_sync(gmask, my, base + 1);
        int s2 = __shfl_sync(gmask, my, base + 2);
        int s3 = __shfl_sync(gmask, my, base + 3);
        c0 = __hadd2(c0, H2[s0 * 4 + f2]);
        c1 = __hadd2(c1, H2[s1 * 4 + f2]);
        c2 = __hadd2(c2, H2[s2 * 4 + f2]);
        c3 = __hadd2(c3, H2[s3 * 4 + f2]);
    }
    if (e < cnt) {
        int rem = cnt - e;                            // 1..3
        int my = __ldg(&adj[e + f2]);                 // in-bounds (padded buffer)
        #pragma unroll
        for (int j = 0; j < 3; j++) {
            int sj = __shfl_sync(gmask, my, base + j);
            if (j < rem) c0 = __hadd2(c0, H2[sj * 4 + f2]);
        }
    }
    __half2 tot = __hadd2(__hadd2(c0, c1), __hadd2(c2, c3));
    float2 sv = __half22float2(tot);

    float dinv_d = rsqrtf((float)(cnt + 1));
    out[node * NL + 2 * f2] = expf(dinv_d * sv.x) + 1.0f;
    if (f2 < 3)
        out[node * NL + 2 * f2 + 1] = expf(dinv_d * sv.y) + 1.0f;
    if (f2 == 3) g_deg[node] = 0;                     // self-clean for next launch
}

// ---------------- launcher ---------------------------------------------------
extern "C" void kernel_launch(void* const* d_in, const int* in_sizes, int n_in,
                              void* d_out, int out_size) {
    const float* x  = (const float*)d_in[0];   // [N,256]
    const float* W0 = (const float*)d_in[1];   // [256,16]
    const float* W1 = (const float*)d_in[2];   // [16,7]
    const int*   ei = (const int*)d_in[3];     // [2,E]
    int E = in_sizes[3] / 2;
    const int* src = ei;
    const int* dst = ei + E;
    float* out = (float*)d_out;

    // Lazily created side stream + events for a fork-join inside graph capture.
    static cudaStream_t s2 = nullptr;
    static cudaEvent_t evFork = nullptr, evJoin = nullptr;
    if (s2 == nullptr) {
        cudaStreamCreateWithFlags(&s2, cudaStreamNonBlocking);
        cudaEventCreateWithFlags(&evFork, cudaEventDisableTiming);
        cudaEventCreateWithFlags(&evJoin, cudaEventDisableTiming);
    }

    int Q = (E + 3) / 4;

    // fork: fill enqueued FIRST (likely branch pole -> starts first),
    // gemm1 (unscaled, independent of g_deg) runs concurrently on s2
    cudaEventRecord(evFork, 0);
    cudaStreamWaitEvent(s2, evFork, 0);
    k_fill  <<<(Q + 255) / 256, 256>>>(src, dst, E, Q);
    k_gemm1 <<<(NN + 255) / 256, 256, 0, s2>>>(x, W0);
    cudaEventRecord(evJoin, s2);
    cudaStreamWaitEvent(0, evJoin, 0);
    // join: everything below depends on both branches
    k_scale <<<(NN * 2 + 255) / 256, 256>>>();
    k_conv1 <<<NSM * 6, 256>>>(W1);                  // persistent: exactly 1 wave
    k_conv2 <<<(NN * 4 + 255) / 256, 256>>>(out);
}

// round 16
// speedup vs baseline: 1.4469x; 1.3860x over previous
#include <cuda_runtime.h>
#include <cuda_fp16.h>
#include <math.h>

#define NN   100000
#define EMAX 3200000
#define FIN  256
#define CH   16
#define NL   7
#define PAD  96          // bucket capacity; P(any deg>96) ~ 1e-13 for Poisson(32)
#define NSM  148

// ---------------- scratch (static __device__, no cudaMalloc) ----------------
// Invariant: g_deg all-zero at entry of every launch (static init covers call 1;
// k_conv2 resets it at the end of each launch).
__device__ int g_deg[NN];
__device__ __align__(128) int    g_buf[NN * PAD + 16];  // +16 pad for coop tail reads
__device__ __align__(16)  __half g_h[NN * CH];      // x@W0 fp16 (unscaled, then scaled in place)
__device__ __align__(16)  __half g_h2[NN * 8];      // dinv-scaled layer-2 input, fp16 [N,8]

// ---------------- packed f32x2 helpers --------------------------------------
__device__ __forceinline__ void ffma2(unsigned long long& d,
                                      unsigned long long a, unsigned long long b) {
    asm("fma.rn.f32x2 %0, %1, %2, %0;" : "+l"(d) : "l"(a), "l"(b));
}
__device__ __forceinline__ unsigned long long pack2(float v) {
    unsigned long long r;
    asm("mov.b64 %0, {%1, %1};" : "=l"(r) : "f"(v));
    return r;
}
__device__ __forceinline__ float2 unpack2(unsigned long long v) {
    float2 r;
    asm("mov.b64 {%0, %1}, %2;" : "=f"(r.x), "=f"(r.y) : "l"(v));
    return r;
}

// ---------------- 1. scatter edges into padded buckets (int4, 4 edges/thr) --
__global__ void k_fill(const int* __restrict__ src, const int* __restrict__ dst,
                       int E, int Q) {
    int i = blockIdx.x * blockDim.x + threadIdx.x;
    if (i >= Q) return;
    int b = i * 4;
    if (b + 3 < E) {
        int4 s4 = __ldg((const int4*)src + i);
        int4 d4 = __ldg((const int4*)dst + i);
        int p0 = atomicAdd(&g_deg[d4.x], 1);
        if (p0 < PAD) g_buf[d4.x * PAD + p0] = s4.x;
        int p1 = atomicAdd(&g_deg[d4.y], 1);
        if (p1 < PAD) g_buf[d4.y * PAD + p1] = s4.y;
        int p2 = atomicAdd(&g_deg[d4.z], 1);
        if (p2 < PAD) g_buf[d4.z * PAD + p2] = s4.z;
        int p3 = atomicAdd(&g_deg[d4.w], 1);
        if (p3 < PAD) g_buf[d4.w * PAD + p3] = s4.w;
    } else {
        for (int j = b; j < E; j++) {
            int s = src[j], d = dst[j];
            int pos = atomicAdd(&g_deg[d], 1);
            if (pos < PAD) g_buf[d * PAD + pos] = s;
        }
    }
}

// ---------------- 2. h = x @ W0 (UNSCALED), fp16 out, f32x2 FMA (R12) -------
// Runs concurrently with k_fill (does not touch g_deg).
__global__ void k_gemm1(const float* __restrict__ x, const float* __restrict__ W0) {
    __shared__ __align__(16) float W0s[FIN * CH];
    int t = threadIdx.x;
    for (int i = t; i < FIN * CH; i += 256) W0s[i] = W0[i];
    __syncthreads();
    int r = blockIdx.x * 256 + t;
    if (r >= NN) return;

    const float4* xr = (const float4*)(x + (size_t)r * FIN);
    const unsigned long long* W8 = (const unsigned long long*)W0s;

    unsigned long long acc2[8];
    #pragma unroll
    for (int j = 0; j < 8; j++) acc2[j] = 0ull;

    #pragma unroll 4
    for (int i4 = 0; i4 < FIN / 4; i4++) {
        float4 v = xr[i4];
        #pragma unroll
        for (int k = 0; k < 4; k++) {
            float xv = (k == 0) ? v.x : (k == 1) ? v.y : (k == 2) ? v.z : v.w;
            unsigned long long xp = pack2(xv);
            const unsigned long long* wr = W8 + (size_t)(i4 * 4 + k) * 8;
            #pragma unroll
            for (int j = 0; j < 8; j++) ffma2(acc2[j], xp, wr[j]);
        }
    }
    __half2 hv[8];
    #pragma unroll
    for (int j = 0; j < 8; j++) {
        float2 p = unpack2(acc2[j]);
        hv[j] = __floats2half2_rn(p.x, p.y);
    }
    uint4* hr = (uint4*)(g_h + (size_t)r * CH);
    hr[0] = *(uint4*)&hv[0];
    hr[1] = *(uint4*)&hv[4];
}

// ---------------- 3. scale h rows in place by dinv[row], uint4 --------------
__global__ void k_scale() {
    int i = blockIdx.x * 256 + threadIdx.x;      // NN*2 uint4 words (8 halfs each)
    if (i >= NN * 2) return;
    int r = i >> 1;
    float s = rsqrtf((float)(g_deg[r] + 1));     // +1 = self loop
    uint4 v = ((const uint4*)g_h)[i];
    __half2* hp = (__half2*)&v;
    #pragma unroll
    for (int j = 0; j < 4; j++) {
        float2 p = __half22float2(hp[j]);
        hp[j] = __floats2half2_rn(p.x * s, p.y * s);
    }
    ((uint4*)g_h)[i] = v;
}

// ---------------- 4. conv1 + relu + 16->7 dense, fused (persistent) ---------
// 4 lanes per node (8 nodes/warp), grid-stride over nodes. Lane q holds
// features 4q..4q+3 via one 8-byte gather.
__global__ void __launch_bounds__(256, 6) k_conv1(const float* __restrict__ W1) {
    __shared__ float W1s[CH * NL];
    int t = threadIdx.x;
    if (t < CH * NL) W1s[t] = W1[t];
    __syncthreads();

    int lane = t & 31;
    int q    = lane & 3;                              // feature-quad index
    int base = lane & 28;                             // group base within warp
    unsigned gmask = 0xFu << base;                    // 4-lane group mask
    int node0  = (blockIdx.x * blockDim.x + t) >> 2;
    int stride = (gridDim.x * blockDim.x) >> 2;

    const unsigned long long* H64 = (const unsigned long long*)g_h;  // row = 4 ull
    __half2* H2o = (__half2*)g_h2;

    for (int node = node0; node < NN; node += stride) {
        int cnt = g_deg[node];
        float dinv_d = rsqrtf((float)(cnt + 1));
        const int* adj = g_buf + (size_t)node * PAD;

        // self-loop term (row pre-scaled by dinv[src])
        unsigned long long sw = __ldg(&H64[(size_t)node * 4 + q]);
        float2 slo = __half22float2(*(__half2*)&sw);
        float2 shi = __half22float2(*((__half2*)&sw + 1));
        float a0 = slo.x, a1 = slo.y, a2 = shi.x, a3 = shi.y;
        float b0 = 0.f, b1 = 0.f, b2 = 0.f, b3 = 0.f;

        int n4 = cnt & ~3;
        int e = 0;
        for (; e < n4; e += 4) {
            int my = __ldg(&adj[e + q]);              // 16B per group
            int s0 = __shfl_sync(gmask, my, base + 0);
            int s1 = __shfl_sync(gmask, my, base + 1);
            int s2 = __shfl_sync(gmask, my, base + 2);
            int s3 = __shfl_sync(gmask, my, base + 3);
            unsigned long long w0 = __ldg(&H64[(size_t)s0 * 4 + q]);
            unsigned long long w1 = __ldg(&H64[(size_t)s1 * 4 + q]);
            unsigned long long w2 = __ldg(&H64[(size_t)s2 * 4 + q]);
            unsigned long long w3 = __ldg(&H64[(size_t)s3 * 4 + q]);
            float2 l0 = __half22float2(*(__half2*)&w0), h0 = __half22float2(*((__half2*)&w0 + 1));
            float2 l1 = __half22float2(*(__half2*)&w1), h1 = __half22float2(*((__half2*)&w1 + 1));
            float2 l2 = __half22float2(*(__half2*)&w2), h2 = __half22float2(*((__half2*)&w2 + 1));
            float2 l3 = __half22float2(*(__half2*)&w3), h3 = __half22float2(*((__half2*)&w3 + 1));
            a0 += l0.x; a1 += l0.y; a2 += h0.x; a3 += h0.y;
            b0 += l1.x; b1 += l1.y; b2 += h1.x; b3 += h1.y;
            a0 += l2.x; a1 += l2.y; a2 += h2.x; a3 += h2.y;
            b0 += l3.x; b1 += l3.y; b2 += h3.x; b3 += h3.y;
        }
        if (e < cnt) {                                // tail: 1..3 edges
            int rem = cnt - e;
            int my = __ldg(&adj[e + q]);              // in-bounds (padded buffer)
            #pragma unroll
            for (int j = 0; j < 3; j++) {
                int sj = __shfl_sync(gmask, my, base + j);
                if (j < rem) {
                    unsigned long long w = __ldg(&H64[(size_t)sj * 4 + q]);
                    float2 l = __half22float2(*(__half2*)&w);
                    float2 h = __half22float2(*((__half2*)&w + 1));
                    a0 += l.x; a1 += l.y; a2 += h.x; a3 += h.y;
                }
            }
        }
        float rv[4];
        rv[0] = fmaxf(dinv_d * (a0 + b0), 0.f);
        rv[1] = fmaxf(dinv_d * (a1 + b1), 0.f);
        rv[2] = fmaxf(dinv_d * (a2 + b2), 0.f);
        rv[3] = fmaxf(dinv_d * (a3 + b3), 0.f);

        // 16->7 dense: lane q produces outputs 2q, 2q+1 (out 7 -> 0)
        int j0 = 2 * q;
        int j1 = (2 * q + 1 < NL) ? 2 * q + 1 : 0;
        float o0 = 0.f, o1 = 0.f;
        #pragma unroll
        for (int m = 0; m < 4; m++) {
            float r0 = __shfl_sync(gmask, rv[0], base + m);
            float r1 = __shfl_sync(gmask, rv[1], base + m);
            float r2 = __shfl_sync(gmask, rv[2], base + m);
            float r3 = __shfl_sync(gmask, rv[3], base + m);
            o0 = fmaf(r0, W1s[(4 * m + 0) * NL + j0], o0);
            o0 = fmaf(r1, W1s[(4 * m + 1) * NL + j0], o0);
            o0 = fmaf(r2, W1s[(4 * m + 2) * NL + j0], o0);
            o0 = fmaf(r3, W1s[(4 * m + 3) * NL + j0], o0);
            o1 = fmaf(r0, W1s[(4 * m + 0) * NL + j1], o1);
            o1 = fmaf(r1, W1s[(4 * m + 1) * NL + j1], o1);
            o1 = fmaf(r2, W1s[(4 * m + 2) * NL + j1], o1);
            o1 = fmaf(r3, W1s[(4 * m + 3) * NL + j1], o1);
        }
        float hi = (2 * q + 1 < NL) ? dinv_d * o1 : 0.f;
        H2o[(size_t)node * 4 + q] = __floats2half2_rn(dinv_d * o0, hi);
    }
}

// ---------------- 5. conv2 + exp + 1; resets g_deg --------------------------
// 4 lanes per node (8 nodes/warp), half2 gathers + HADD2, direct indexing.
__global__ void k_conv2(float* __restrict__ out) {
    int t    = blockIdx.x * blockDim.x + threadIdx.x;
    int lane = threadIdx.x & 31;
    int f2   = lane & 3;
    int base = lane & 28;
    unsigned gmask = 0xFu << base;
    int node = t >> 2;
    if (node >= NN) return;

    int cnt = g_deg[node];
    const int* adj = g_buf + (size_t)node * PAD;
    const __half2* H2 = (const __half2*)g_h2;

    __half2 z2 = __floats2half2_rn(0.f, 0.f);
    __half2 c0 = H2[node * 4 + f2];                   // self-loop term
    __half2 c1 = z2, c2 = z2, c3 = z2;

    int n4 = cnt & ~3;
    int e = 0;
    for (; e < n4; e += 4) {
        int my = __ldg(&adj[e + f2]);                 // 16B per group
        int s0 = __shfl_sync(gmask, my, base + 0);
        int s1 = __shfl_sync(gmask, my, base + 1);
        int s2 = __shfl_sync(gmask, my, base + 2);
        int s3 = __shfl_sync(gmask, my, base + 3);
        c0 = __hadd2(c0, H2[s0 * 4 + f2]);
        c1 = __hadd2(c1, H2[s1 * 4 + f2]);
        c2 = __hadd2(c2, H2[s2 * 4 + f2]);
        c3 = __hadd2(c3, H2[s3 * 4 + f2]);
    }
    if (e < cnt) {
        int rem = cnt - e;                            // 1..3
        int my = __ldg(&adj[e + f2]);                 // in-bounds (padded buffer)
        #pragma unroll
        for (int j = 0; j < 3; j++) {
            int sj = __shfl_sync(gmask, my, base + j);
            if (j < rem) c0 = __hadd2(c0, H2[sj * 4 + f2]);
        }
    }
    __half2 tot = __hadd2(__hadd2(c0, c1), __hadd2(c2, c3));
    float2 sv = __half22float2(tot);

    float dinv_d = rsqrtf((float)(cnt + 1));
    out[node * NL + 2 * f2] = expf(dinv_d * sv.x) + 1.0f;
    if (f2 < 3)
        out[node * NL + 2 * f2 + 1] = expf(dinv_d * sv.y) + 1.0f;
    if (f2 == 3) g_deg[node] = 0;                     // self-clean for next launch
}

// ---------------- launcher ---------------------------------------------------
extern "C" void kernel_launch(void* const* d_in, const int* in_sizes, int n_in,
                              void* d_out, int out_size) {
    const float* x  = (const float*)d_in[0];   // [N,256]
    const float* W0 = (const float*)d_in[1];   // [256,16]
    const float* W1 = (const float*)d_in[2];   // [16,7]
    const int*   ei = (const int*)d_in[3];     // [2,E]
    int E = in_sizes[3] / 2;
    const int* src = ei;
    const int* dst = ei + E;
    float* out = (float*)d_out;

    // Lazily created side stream + events for a fork-join inside graph capture.
    static cudaStream_t s2 = nullptr;
    static cudaEvent_t evFork = nullptr, evJoin = nullptr;
    if (s2 == nullptr) {
        cudaStreamCreateWithFlags(&s2, cudaStreamNonBlocking);
        cudaEventCreateWithFlags(&evFork, cudaEventDisableTiming);
        cudaEventCreateWithFlags(&evJoin, cudaEventDisableTiming);
    }

    int Q = (E + 3) / 4;

    // fork: gemm1 enqueued FIRST (small grid grabs SMs, fill backfills -> true
    // overlap; the reverse order serializes the branches — measured R15).
    cudaEventRecord(evFork, 0);
    cudaStreamWaitEvent(s2, evFork, 0);
    k_gemm1 <<<(NN + 255) / 256, 256, 0, s2>>>(x, W0);
    k_fill  <<<(Q + 255) / 256, 256>>>(src, dst, E, Q);
    cudaEventRecord(evJoin, s2);
    cudaStreamWaitEvent(0, evJoin, 0);
    // join: everything below depends on both branches
    k_scale <<<(NN * 2 + 255) / 256, 256>>>();
    k_conv1 <<<NSM * 6, 256>>>(W1);                  // persistent: exactly 1 wave
    k_conv2 <<<(NN * 4 + 255) / 256, 256>>>(out);
}